// round 1
// baseline (speedup 1.0000x reference)
#include <cuda_runtime.h>

// Problem shapes (fixed by setup_inputs)
#define NROWS   2048          // rows of x
#define DDIM    256           // feature dim (K)
#define TTRK    256           // number of tracks T
#define QQ      64            // Q
#define TQCOLS  16384         // T*Q columns from y
#define NBCOLS  (TQCOLS + NROWS)  // 18432 combined columns [yf ; x]

static __device__ float g_rowacc[4 * NROWS];  // [0]=rxy_tot [1]=rxy_pos [2]=rxx_tot [3]=rxx_pos_full
static __device__ float g_num[TTRK];
static __device__ float g_den[TTRK];
static __device__ int   g_cnt[TTRK];

__device__ __forceinline__ float inv_temp() { return 1.0f / 0.3f; }

// ---------------------------------------------------------------------------
// Kernel 0: zero scratch (must run every launch; graph replays reuse scratch)
// ---------------------------------------------------------------------------
__global__ void zero_kernel() {
    int i = blockIdx.x * blockDim.x + threadIdx.x;
    if (i < 4 * NROWS) g_rowacc[i] = 0.0f;
    if (i < TTRK) { g_num[i] = 0.0f; g_den[i] = 0.0f; g_cnt[i] = 0; }
}

// ---------------------------------------------------------------------------
// Kernel 1: fused exp-GEMM + masked per-row reduction.
// C = x @ B^T where B = [yf ; x] (NBCOLS x DDIM). For each element:
//   s = exp(c / TEMP); accumulate per-row total and same-track sums.
// Tiling: BM=BN=128, BK=8, 256 threads, 8x8 per thread.
// Grid x = column tiles (144: first 128 are xy, last 16 are xx), grid y = row tiles.
// ---------------------------------------------------------------------------
#define BM 128
#define BN 128
#define BK 8
#define TM 8
#define TN 8

__global__ __launch_bounds__(256, 2)
void gemm_exp_kernel(const float* __restrict__ x,
                     const int*   __restrict__ trk,
                     const float* __restrict__ y) {
    __shared__ float As[BK][BM];
    __shared__ float Bs[BK][BN];
    __shared__ int   sColT[BN];
    __shared__ int   sRowT[BM];

    const int tid = threadIdx.x;
    const int tx  = tid & 15;     // 0..15 -> column group
    const int ty  = tid >> 4;     // 0..15 -> row group
    const int rowBase = blockIdx.y * BM;
    const int colBase = blockIdx.x * BN;
    const bool isXY = (colBase < TQCOLS);

    const float* Bbase = isXY ? (y + (size_t)colBase * DDIM)
                              : (x + (size_t)(colBase - TQCOLS) * DDIM);

    // Track ids for this tile's rows and columns (256 threads cover 128+128)
    if (tid < BN) {
        int j = colBase + tid;
        sColT[tid] = isXY ? (j & (TTRK - 1)) : trk[j - TQCOLS];
    } else {
        sRowT[tid - BN] = trk[rowBase + (tid - BN)];
    }

    float acc[TM][TN];
    #pragma unroll
    for (int i = 0; i < TM; i++)
        #pragma unroll
        for (int j = 0; j < TN; j++)
            acc[i][j] = 0.0f;

    // Loader mapping: each thread loads one float4 of A and one of B per k-chunk
    const int lrow = tid >> 1;          // 0..127
    const int lkg  = (tid & 1) * 4;     // 0 or 4
    const float* aPtr = x     + (size_t)(rowBase + lrow) * DDIM + lkg;
    const float* bPtr = Bbase + (size_t)lrow * DDIM + lkg;

    for (int k0 = 0; k0 < DDIM; k0 += BK) {
        float4 av = *reinterpret_cast<const float4*>(aPtr + k0);
        float4 bv = *reinterpret_cast<const float4*>(bPtr + k0);
        __syncthreads();  // previous iteration's compute done before overwrite
        As[lkg + 0][lrow] = av.x; As[lkg + 1][lrow] = av.y;
        As[lkg + 2][lrow] = av.z; As[lkg + 3][lrow] = av.w;
        Bs[lkg + 0][lrow] = bv.x; Bs[lkg + 1][lrow] = bv.y;
        Bs[lkg + 2][lrow] = bv.z; Bs[lkg + 3][lrow] = bv.w;
        __syncthreads();

        #pragma unroll
        for (int k = 0; k < BK; k++) {
            float4 a0 = *reinterpret_cast<const float4*>(&As[k][ty * TM]);
            float4 a1 = *reinterpret_cast<const float4*>(&As[k][ty * TM + 4]);
            float4 b0 = *reinterpret_cast<const float4*>(&Bs[k][tx * TN]);
            float4 b1 = *reinterpret_cast<const float4*>(&Bs[k][tx * TN + 4]);
            float a[TM] = {a0.x, a0.y, a0.z, a0.w, a1.x, a1.y, a1.z, a1.w};
            float b[TN] = {b0.x, b0.y, b0.z, b0.w, b1.x, b1.y, b1.z, b1.w};
            #pragma unroll
            for (int i = 0; i < TM; i++)
                #pragma unroll
                for (int j = 0; j < TN; j++)
                    acc[i][j] = fmaf(a[i], b[j], acc[i][j]);
        }
    }

    // Epilogue: exp + masked per-row sums
    int rt[TM];
    #pragma unroll
    for (int i = 0; i < TM; i++) rt[i] = sRowT[ty * TM + i];
    int ct[TN];
    #pragma unroll
    for (int j = 0; j < TN; j++) ct[j] = sColT[tx * TN + j];

    float tot[TM], pos[TM];
    #pragma unroll
    for (int i = 0; i < TM; i++) { tot[i] = 0.0f; pos[i] = 0.0f; }

    #pragma unroll
    for (int i = 0; i < TM; i++) {
        #pragma unroll
        for (int j = 0; j < TN; j++) {
            float s = __expf(acc[i][j] * inv_temp());
            tot[i] += s;
            pos[i] += (ct[j] == rt[i]) ? s : 0.0f;
        }
    }

    // Reduce across the 16 column-group threads sharing each row (lanes of same ty
    // are 16 contiguous lanes within a warp since tid = ty*16 + tx).
    #pragma unroll
    for (int i = 0; i < TM; i++) {
        #pragma unroll
        for (int off = 8; off > 0; off >>= 1) {
            tot[i] += __shfl_down_sync(0xffffffffu, tot[i], off, 16);
            pos[i] += __shfl_down_sync(0xffffffffu, pos[i], off, 16);
        }
    }

    if (tx == 0) {
        const int base = isXY ? 0 : 2 * NROWS;
        #pragma unroll
        for (int i = 0; i < TM; i++) {
            int row = rowBase + ty * TM + i;
            atomicAdd(&g_rowacc[base + row], tot[i]);
            atomicAdd(&g_rowacc[base + NROWS + row], pos[i]);
        }
    }
}

// ---------------------------------------------------------------------------
// Kernel 2: per-row finalize. diag_i = exp(||x_i||^2/TEMP); compute num_i/den_i
// and accumulate per-track numerator/denominator/count.
// One warp per row; grid = NROWS/8 blocks of 256 threads.
// ---------------------------------------------------------------------------
__global__ void finalize_rows(const float* __restrict__ x,
                              const int*   __restrict__ trk) {
    const int warpId = threadIdx.x >> 5;
    const int lane   = threadIdx.x & 31;
    const int row    = blockIdx.x * 8 + warpId;
    const float* xr = x + (size_t)row * DDIM;

    float ssq = 0.0f;
    #pragma unroll
    for (int s = 0; s < DDIM; s += 32) {
        float v = xr[lane + s];
        ssq = fmaf(v, v, ssq);
    }
    #pragma unroll
    for (int off = 16; off > 0; off >>= 1)
        ssq += __shfl_down_sync(0xffffffffu, ssq, off);

    if (lane == 0) {
        float diag = __expf(ssq * inv_temp());
        float rxyT = g_rowacc[row];
        float rxyP = g_rowacc[NROWS + row];
        float rxxT = g_rowacc[2 * NROWS + row];
        float rxxP = g_rowacc[3 * NROWS + row];  // includes diagonal
        float num = rxyP + 0.5f * (rxxP - diag);
        float den = (rxyT - rxyP) + (rxxT - rxxP);
        int t = trk[row];
        atomicAdd(&g_num[t], num);
        atomicAdd(&g_den[t], den);
        atomicAdd(&g_cnt[t], 1);
    }
}

// ---------------------------------------------------------------------------
// Kernel 3: per-track loss + mean over present tracks. Single block of 256.
// ---------------------------------------------------------------------------
__global__ void finalize_loss(float* __restrict__ out) {
    __shared__ float sl[TTRK];
    __shared__ int   sp[TTRK];
    const int t = threadIdx.x;
    const int c = g_cnt[t];
    float loss = 0.0f;
    if (c > 0) {
        float n = g_num[t];
        float d = g_den[t];
        loss = -logf(n / (d + n));
    }
    sl[t] = loss;
    sp[t] = (c > 0) ? 1 : 0;
    __syncthreads();
    #pragma unroll
    for (int off = 128; off > 0; off >>= 1) {
        if (t < off) { sl[t] += sl[t + off]; sp[t] += sp[t + off]; }
        __syncthreads();
    }
    if (t == 0) out[0] = sl[0] / (float)sp[0];
}

// ---------------------------------------------------------------------------
extern "C" void kernel_launch(void* const* d_in, const int* in_sizes, int n_in,
                              void* d_out, int out_size) {
    const float* x   = (const float*)d_in[0];
    const int*   trk = (const int*)d_in[1];
    const float* y   = (const float*)d_in[2];
    float* out = (float*)d_out;

    zero_kernel<<<(4 * NROWS + 255) / 256, 256>>>();

    dim3 grid(NBCOLS / BN, NROWS / BM);  // 144 x 16
    gemm_exp_kernel<<<grid, 256>>>(x, trk, y);

    finalize_rows<<<NROWS / 8, 256>>>(x, trk);
    finalize_loss<<<1, 256>>>(out);
}

// round 4
// speedup vs baseline: 6.6000x; 6.6000x over previous
#include <cuda_runtime.h>
#include <cuda_bf16.h>
#include <cstdint>

// Problem shapes (fixed by setup_inputs)
#define NROWS   2048
#define DDIM    256
#define TTRK    256
#define TQCOLS  16384
#define NBCOLS  (TQCOLS + NROWS)   // 18432

#define BM 128
#define BN 128
#define BK 32
#define NCHUNKS (DDIM / BK)        // 8

static __device__ float g_rowacc[4 * NROWS];
static __device__ float g_num[TTRK];
static __device__ float g_den[TTRK];
static __device__ int   g_cnt[TTRK];
static __device__ __nv_bfloat16 g_comb[(size_t)NBCOLS * DDIM];  // [yf ; x] in bf16

__device__ __forceinline__ float inv_temp() { return 1.0f / 0.3f; }

// ---------------------------------------------------------------------------
__device__ __forceinline__ uint32_t smem_u32(const void* p) {
    uint32_t a;
    asm("{ .reg .u64 t; cvta.to.shared.u64 t, %1; cvt.u32.u64 %0, t; }" : "=r"(a) : "l"(p));
    return a;
}

#define CP16(sa, ga) \
    asm volatile("cp.async.cg.shared.global [%0], [%1], 16;" :: "r"(sa), "l"(ga) : "memory")
#define CP_COMMIT() asm volatile("cp.async.commit_group;" ::: "memory")
#define CP_WAIT1()  asm volatile("cp.async.wait_group 1;" ::: "memory")
#define CP_WAIT0()  asm volatile("cp.async.wait_group 0;" ::: "memory")

#define LDMX4(r, addr) \
    asm volatile("ldmatrix.sync.aligned.m8n8.x4.shared.b16 {%0,%1,%2,%3}, [%4];" \
        : "=r"((r)[0]), "=r"((r)[1]), "=r"((r)[2]), "=r"((r)[3]) : "r"(addr))

__device__ __forceinline__ void mma_bf16(float* d, const uint32_t* a,
                                         uint32_t b0, uint32_t b1) {
    asm volatile(
        "mma.sync.aligned.m16n8k16.row.col.f32.bf16.bf16.f32 "
        "{%0,%1,%2,%3},{%4,%5,%6,%7},{%8,%9},{%0,%1,%2,%3};"
        : "+f"(d[0]), "+f"(d[1]), "+f"(d[2]), "+f"(d[3])
        : "r"(a[0]), "r"(a[1]), "r"(a[2]), "r"(a[3]), "r"(b0), "r"(b1));
}

// smem tile: 128 rows x 32 bf16 (64B/row = 4 x 16B chunks), XOR-swizzled so
// ldmatrix (8 rows x 16B) and 128B STS phases are both conflict-free.
__device__ __forceinline__ uint32_t swz(int row, int ch) {
    return (uint32_t)(row * 64 + ((ch ^ ((row >> 1) & 3)) << 4));
}

// ---------------------------------------------------------------------------
// Kernel 0: convert [y; x] -> bf16 comb buffer + zero scratch
// ---------------------------------------------------------------------------
__global__ void prep_kernel(const float* __restrict__ x,
                            const float* __restrict__ y) {
    int idx = blockIdx.x * blockDim.x + threadIdx.x;
    if (idx < 4 * NROWS) g_rowacc[idx] = 0.0f;
    if (idx < TTRK) { g_num[idx] = 0.0f; g_den[idx] = 0.0f; g_cnt[idx] = 0; }

    // 8 elements per thread
    int row = idx >> 5;
    int col = (idx & 31) * 8;
    const float* src = (row < TQCOLS)
        ? (y + (size_t)row * DDIM + col)
        : (x + (size_t)(row - TQCOLS) * DDIM + col);
    float4 v0 = *(const float4*)src;
    float4 v1 = *(const float4*)(src + 4);
    __nv_bfloat16 o[8];
    o[0] = __float2bfloat16_rn(v0.x); o[1] = __float2bfloat16_rn(v0.y);
    o[2] = __float2bfloat16_rn(v0.z); o[3] = __float2bfloat16_rn(v0.w);
    o[4] = __float2bfloat16_rn(v1.x); o[5] = __float2bfloat16_rn(v1.y);
    o[6] = __float2bfloat16_rn(v1.z); o[7] = __float2bfloat16_rn(v1.w);
    *(uint4*)(g_comb + (size_t)row * DDIM + col) = *(const uint4*)o;
}

// ---------------------------------------------------------------------------
// Kernel 1: fused bf16 mma.sync exp-GEMM + masked per-row reductions.
// Grid (144, 16): 144 col tiles (128 xy + 16 xx), 16 row tiles. 256 threads.
// Warp grid 2(M) x 4(N); warp tile 64x32; m16n8k16 bf16 -> f32.
// ---------------------------------------------------------------------------
__global__ __launch_bounds__(256, 2)
void gemm_mma(const int* __restrict__ trk) {
    __shared__ __align__(128) uint8_t sA[2][BM * 64];
    __shared__ __align__(128) uint8_t sB[2][BN * 64];
    __shared__ int sColT[BN];
    __shared__ int sRowT[BM];

    const int tid = threadIdx.x;
    const int w = tid >> 5, l = tid & 31;
    const int wm = w & 1, wn = w >> 1;
    const int rowBase = blockIdx.y * BM;
    const int colBase = blockIdx.x * BN;
    const bool isXY = (colBase < TQCOLS);

    if (tid < BN) {
        int j = colBase + tid;
        sColT[tid] = isXY ? (j & (TTRK - 1)) : trk[j - TQCOLS];
    } else {
        sRowT[tid - BN] = trk[rowBase + (tid - BN)];
    }

    const uint32_t aB0 = smem_u32(sA[0]), aB1 = smem_u32(sA[1]);
    const uint32_t bB0 = smem_u32(sB[0]), bB1 = smem_u32(sB[1]);

    // loader mapping: idx -> (row, 16B-chunk); 2 iters cover 128x4 chunks
    const int lr0 = tid >> 2, lc = tid & 3;
    const __nv_bfloat16* gA = g_comb + (size_t)(TQCOLS + rowBase) * DDIM;
    const __nv_bfloat16* gB = g_comb + (size_t)colBase * DDIM;

#define LOAD_CHUNK(c, aBase, bBase) do {                                        \
    int k0 = (c) * BK;                                                          \
    _Pragma("unroll")                                                           \
    for (int it = 0; it < 2; it++) {                                            \
        int r = lr0 + it * 64;                                                  \
        CP16((aBase) + swz(r, lc), gA + (size_t)r * DDIM + k0 + lc * 8);        \
        CP16((bBase) + swz(r, lc), gB + (size_t)r * DDIM + k0 + lc * 8);        \
    } } while (0)

    float acc[4][4][4];
    #pragma unroll
    for (int mi = 0; mi < 4; mi++)
        #pragma unroll
        for (int nj = 0; nj < 4; nj++)
            #pragma unroll
            for (int e = 0; e < 4; e++)
                acc[mi][nj][e] = 0.0f;

    LOAD_CHUNK(0, aB0, bB0);
    CP_COMMIT();

    for (int c = 0; c < NCHUNKS; c++) {
        const int buf = c & 1;
        if (c < NCHUNKS - 1) {
            if (buf == 0) LOAD_CHUNK(c + 1, aB1, bB1);
            else          LOAD_CHUNK(c + 1, aB0, bB0);
            CP_COMMIT();
            CP_WAIT1();
        } else {
            CP_WAIT0();
        }
        __syncthreads();

        const uint32_t aBase = buf ? aB1 : aB0;
        const uint32_t bBase = buf ? bB1 : bB0;

        #pragma unroll
        for (int k16 = 0; k16 < 2; k16++) {
            const int cc0 = k16 * 2;
            uint32_t af[4][4];
            #pragma unroll
            for (int mi = 0; mi < 4; mi++) {
                int row = wm * 64 + mi * 16 + (l & 7) + ((l >> 3) & 1) * 8;
                int ch  = cc0 + (l >> 4);
                LDMX4(af[mi], aBase + swz(row, ch));
            }
            uint32_t bfr[2][4];
            #pragma unroll
            for (int nh = 0; nh < 2; nh++) {
                int row = wn * 32 + nh * 16 + (l & 7) + ((l >> 4) & 1) * 8;
                int ch  = cc0 + ((l >> 3) & 1);
                LDMX4(bfr[nh], bBase + swz(row, ch));
            }
            #pragma unroll
            for (int mi = 0; mi < 4; mi++)
                #pragma unroll
                for (int nj = 0; nj < 4; nj++) {
                    int nh = nj >> 1, bs = (nj & 1) * 2;
                    mma_bf16(acc[mi][nj], af[mi], bfr[nh][bs], bfr[nh][bs + 1]);
                }
        }
        __syncthreads();
    }

    // ---- epilogue: exp + masked row sums ----
    const int t = l & 3, g = l >> 2;
    int ctv[4][2];
    #pragma unroll
    for (int nj = 0; nj < 4; nj++) {
        ctv[nj][0] = sColT[wn * 32 + nj * 8 + 2 * t];
        ctv[nj][1] = sColT[wn * 32 + nj * 8 + 2 * t + 1];
    }
    const int base = isXY ? 0 : 2 * NROWS;

    #pragma unroll
    for (int mi = 0; mi < 4; mi++) {
        const int rtLo = sRowT[wm * 64 + mi * 16 + g];
        const int rtHi = sRowT[wm * 64 + mi * 16 + g + 8];
        float tl = 0.0f, th = 0.0f, pl = 0.0f, ph = 0.0f;
        #pragma unroll
        for (int nj = 0; nj < 4; nj++) {
            float s0 = __expf(acc[mi][nj][0] * inv_temp());
            float s1 = __expf(acc[mi][nj][1] * inv_temp());
            float s2 = __expf(acc[mi][nj][2] * inv_temp());
            float s3 = __expf(acc[mi][nj][3] * inv_temp());
            tl += s0 + s1;
            th += s2 + s3;
            pl += ((ctv[nj][0] == rtLo) ? s0 : 0.0f) + ((ctv[nj][1] == rtLo) ? s1 : 0.0f);
            ph += ((ctv[nj][0] == rtHi) ? s2 : 0.0f) + ((ctv[nj][1] == rtHi) ? s3 : 0.0f);
        }
        // reduce over the 4 lanes (t) sharing each row
        #pragma unroll
        for (int off = 1; off < 4; off <<= 1) {
            tl += __shfl_xor_sync(0xffffffffu, tl, off);
            th += __shfl_xor_sync(0xffffffffu, th, off);
            pl += __shfl_xor_sync(0xffffffffu, pl, off);
            ph += __shfl_xor_sync(0xffffffffu, ph, off);
        }
        if (t == 0) {
            int rLo = rowBase + wm * 64 + mi * 16 + g;
            int rHi = rLo + 8;
            atomicAdd(&g_rowacc[base + rLo], tl);
            atomicAdd(&g_rowacc[base + NROWS + rLo], pl);
            atomicAdd(&g_rowacc[base + rHi], th);
            atomicAdd(&g_rowacc[base + NROWS + rHi], ph);
        }
    }
#undef LOAD_CHUNK
}

// ---------------------------------------------------------------------------
// Kernel 2: per-row finalize. Diagonal from the SAME bf16-rounded x so the
// rxx_pos_full - diag cancellation is exact to fp32 accumulation noise.
// ---------------------------------------------------------------------------
__global__ void finalize_rows(const int* __restrict__ trk) {
    const int warpId = threadIdx.x >> 5;
    const int lane   = threadIdx.x & 31;
    const int row    = blockIdx.x * 8 + warpId;
    const __nv_bfloat16* xr = g_comb + (size_t)(TQCOLS + row) * DDIM;

    float ssq = 0.0f;
    #pragma unroll
    for (int s = 0; s < DDIM; s += 32) {
        float v = __bfloat162float(xr[lane + s]);
        ssq = fmaf(v, v, ssq);
    }
    #pragma unroll
    for (int off = 16; off > 0; off >>= 1)
        ssq += __shfl_down_sync(0xffffffffu, ssq, off);

    if (lane == 0) {
        float diag = __expf(ssq * inv_temp());
        float rxyT = g_rowacc[row];
        float rxyP = g_rowacc[NROWS + row];
        float rxxT = g_rowacc[2 * NROWS + row];
        float rxxP = g_rowacc[3 * NROWS + row];
        float num = rxyP + 0.5f * (rxxP - diag);
        float den = (rxyT - rxyP) + (rxxT - rxxP);
        int tkr = trk[row];
        atomicAdd(&g_num[tkr], num);
        atomicAdd(&g_den[tkr], den);
        atomicAdd(&g_cnt[tkr], 1);
    }
}

__global__ void finalize_loss(float* __restrict__ out) {
    __shared__ float sl[TTRK];
    __shared__ int   sp[TTRK];
    const int t = threadIdx.x;
    const int c = g_cnt[t];
    float loss = 0.0f;
    if (c > 0) loss = -logf(g_num[t] / (g_den[t] + g_num[t]));
    sl[t] = loss;
    sp[t] = (c > 0) ? 1 : 0;
    __syncthreads();
    #pragma unroll
    for (int off = 128; off > 0; off >>= 1) {
        if (t < off) { sl[t] += sl[t + off]; sp[t] += sp[t + off]; }
        __syncthreads();
    }
    if (t == 0) out[0] = sl[0] / (float)sp[0];
}

// ---------------------------------------------------------------------------
extern "C" void kernel_launch(void* const* d_in, const int* in_sizes, int n_in,
                              void* d_out, int out_size) {
    const float* x   = (const float*)d_in[0];
    const int*   trk = (const int*)d_in[1];
    const float* y   = (const float*)d_in[2];
    float* out = (float*)d_out;

    // one thread per 8 converted elements: 18432*256/8 = 589824 -> 2304 blocks
    prep_kernel<<<(NBCOLS * DDIM / 8) / 256, 256>>>(x, y);

    dim3 grid(NBCOLS / BN, NROWS / BM);  // 144 x 16
    gemm_mma<<<grid, 256>>>(trk);

    finalize_rows<<<NROWS / 8, 256>>>(trk);
    finalize_loss<<<1, 256>>>(out);
}